// round 1
// baseline (speedup 1.0000x reference)
#include <cuda_runtime.h>
#include <math.h>

// Problem constants (fixed by the reference)
#define N_IMG 4
#define C_IN  256
#define HW    16384        // 128*128
#define MLP   128
#define NA    16
#define NB    64
#define ALPHA 300.0f

// Scratch (allocation-free rule: __device__ globals)
__device__ float g_w1t[C_IN * MLP];      // w1 transposed: [k][o]
__device__ float g_A[N_IMG * NA * HW];   // attractor positions A: [img][a][hw]

// ---------------------------------------------------------------------------
// Kernel 0: transpose w1 [o][c] -> [c][o] so SGEMM B-tile loads are coalesced
// and shared stores are conflict-free.
// ---------------------------------------------------------------------------
__global__ void transpose_w1_kernel(const float* __restrict__ w1) {
    int i = blockIdx.x * 256 + threadIdx.x;
    if (i < MLP * C_IN) {
        int o = i >> 8;      // / C_IN
        int k = i & 255;     // % C_IN
        g_w1t[k * MLP + o] = w1[i];
    }
}

// ---------------------------------------------------------------------------
// Kernel 1: fused MLP head.
// GEMM1: hfeat[pix][128] = relu(x[pix][256] @ w1t + b1)   (tiled SGEMM)
// GEMM2: A[pix][16]      = softplus(hfeat @ w2^T + b2)    (smem epilogue)
// Tile: BM=128 pixels x BN=128 outputs x BK=16, 256 threads, 8x8 microtile.
// ---------------------------------------------------------------------------
#define BM 128
#define BK 16
#define HS_LD 132                       // padded row length for hfeat in smem
#define SMEM_FLOATS (BM * HS_LD + NA * MLP)

extern __shared__ float smem[];

__global__ __launch_bounds__(256) void mlp_kernel(
    const float* __restrict__ x,
    const float* __restrict__ b1,
    const float* __restrict__ w2,
    const float* __restrict__ b2)
{
    float* As = smem;            // [BK][BM]   (aliases hs region; re-synced)
    float* Bs = smem + BK * BM;  // [BK][MLP]

    const int tid = threadIdx.x;
    const int pix_base = blockIdx.x * BM;        // 128 | 16384, so one image per block
    const int img = pix_base >> 14;
    const int hw0 = pix_base & (HW - 1);
    const float* xb = x + (size_t)img * C_IN * HW + hw0;

    const int tx = tid & 15;     // output-dim microtile
    const int ty = tid >> 4;     // pixel-dim microtile

    float acc[8][8];
#pragma unroll
    for (int i = 0; i < 8; i++)
#pragma unroll
        for (int j = 0; j < 8; j++) acc[i][j] = 0.0f;

    for (int k0 = 0; k0 < C_IN; k0 += BK) {
#pragma unroll
        for (int i = 0; i < 8; i++) {
            int idx = tid + i * 256;             // 0..2047
            int kk = idx >> 7;                   // 0..15
            int mm = idx & 127;
            As[idx] = xb[(size_t)(k0 + kk) * HW + mm];          // coalesced
            Bs[idx] = g_w1t[(k0 + kk) * MLP + mm];              // coalesced
        }
        __syncthreads();
#pragma unroll
        for (int kk = 0; kk < BK; kk++) {
            float4 a0 = *(const float4*)&As[kk * BM + ty * 8];
            float4 a1 = *(const float4*)&As[kk * BM + ty * 8 + 4];
            float4 bb0 = *(const float4*)&Bs[kk * MLP + tx * 8];
            float4 bb1 = *(const float4*)&Bs[kk * MLP + tx * 8 + 4];
            float av[8] = {a0.x, a0.y, a0.z, a0.w, a1.x, a1.y, a1.z, a1.w};
            float bv[8] = {bb0.x, bb0.y, bb0.z, bb0.w, bb1.x, bb1.y, bb1.z, bb1.w};
#pragma unroll
            for (int i = 0; i < 8; i++)
#pragma unroll
                for (int j = 0; j < 8; j++)
                    acc[i][j] = fmaf(av[i], bv[j], acc[i][j]);
        }
        __syncthreads();
    }

    // ---- epilogue: bias + relu into smem hfeat tile ----
    float b1v[8];
#pragma unroll
    for (int j = 0; j < 8; j++) b1v[j] = b1[tx * 8 + j];

    float* hs = smem;                 // [BM][HS_LD]
    float* ws = smem + BM * HS_LD;    // w2 [NA][MLP]

#pragma unroll
    for (int i = 0; i < 8; i++)
#pragma unroll
        for (int j = 0; j < 8; j++) {
            float v = acc[i][j] + b1v[j];
            hs[(ty * 8 + i) * HS_LD + tx * 8 + j] = v > 0.0f ? v : 0.0f;
        }
#pragma unroll
    for (int i = 0; i < 8; i++) {
        int idx = tid + i * 256;      // 0..2047 = NA*MLP
        ws[idx] = w2[idx];
    }
    __syncthreads();

    // ---- GEMM2 + softplus: one thread per pixel (tid < 128) ----
    if (tid < BM) {
        const int p = tid;
        float acc2[NA];
#pragma unroll
        for (int o = 0; o < NA; o++) acc2[o] = b2[o];

#pragma unroll 4
        for (int k4 = 0; k4 < MLP / 4; k4++) {
            float4 h = *(const float4*)&hs[p * HS_LD + k4 * 4];
#pragma unroll
            for (int o = 0; o < NA; o++) {
                float4 w = *(const float4*)&ws[o * MLP + k4 * 4];
                acc2[o] = fmaf(h.x, w.x, acc2[o]);
                acc2[o] = fmaf(h.y, w.y, acc2[o]);
                acc2[o] = fmaf(h.z, w.z, acc2[o]);
                acc2[o] = fmaf(h.w, w.w, acc2[o]);
            }
        }
#pragma unroll
        for (int o = 0; o < NA; o++) {
            float z = acc2[o];
            // numerically stable softplus, matches jax.nn.softplus in fp32
            float sp = fmaxf(z, 0.0f) + log1pf(__expf(-fabsf(z)));
            g_A[((size_t)img * NA + o) * HW + hw0 + p] = sp;
        }
    }
}

// ---------------------------------------------------------------------------
// Kernel 2: attractor update. One thread per pixel; A[16] in registers,
// loop over the 64 bins. MUFU(EX2)-bound: 16 exps per bin per pixel.
// ---------------------------------------------------------------------------
__global__ __launch_bounds__(256) void attract_kernel(
    const float* __restrict__ b_prev,
    float* __restrict__ out,
    int copies)
{
    int pix = blockIdx.x * blockDim.x + threadIdx.x;   // 0..65535
    int img = pix >> 14;
    int hw = pix & (HW - 1);

    float Av[NA];
#pragma unroll
    for (int a = 0; a < NA; a++)
        Av[a] = g_A[((size_t)img * NA + a) * HW + hw];

    const float* bp = b_prev + (size_t)img * NB * HW + hw;
    float* o0 = out + (size_t)img * NB * HW + hw;
    float* o1 = out + (size_t)N_IMG * NB * HW + (size_t)img * NB * HW + hw;

#pragma unroll 4
    for (int b = 0; b < NB; b++) {
        float bc = bp[(size_t)b * HW];
        float delta = 0.0f;
#pragma unroll
        for (int a = 0; a < NA; a++) {
            float dx = Av[a] - bc;
            float t = dx * dx;
            float e = __expf(-ALPHA * t);
            delta = fmaf(e, dx, delta);
        }
        float r = bc + delta;
        o0[(size_t)b * HW] = r;
        if (copies >= 2) o1[(size_t)b * HW] = r;
    }
}

// ---------------------------------------------------------------------------
// Launch. Inputs (metadata order): x, b_prev, w1, b1, w2, b2.
// Output: (b_new, b_new) -> out_size is 1x or 2x 4*64*128*128 floats.
// ---------------------------------------------------------------------------
extern "C" void kernel_launch(void* const* d_in, const int* in_sizes, int n_in,
                              void* d_out, int out_size) {
    const float* x      = (const float*)d_in[0];
    const float* b_prev = (const float*)d_in[1];
    const float* w1     = (const float*)d_in[2];
    const float* b1     = (const float*)d_in[3];
    const float* w2     = (const float*)d_in[4];
    const float* b2     = (const float*)d_in[5];
    float* out = (float*)d_out;

    const int one_out = N_IMG * NB * HW;          // 4,194,304
    int copies = out_size / one_out;              // 1 or 2

    static bool attr_set = false;
    if (!attr_set) {
        cudaFuncSetAttribute(mlp_kernel,
                             cudaFuncAttributeMaxDynamicSharedMemorySize,
                             SMEM_FLOATS * (int)sizeof(float));
        attr_set = true;
    }

    transpose_w1_kernel<<<(MLP * C_IN + 255) / 256, 256>>>(w1);
    mlp_kernel<<<(N_IMG * HW) / BM, 256, SMEM_FLOATS * sizeof(float)>>>(x, b1, w2, b2);
    attract_kernel<<<(N_IMG * HW) / 256, 256>>>(b_prev, out, copies);
}

// round 3
// speedup vs baseline: 2.7846x; 2.7846x over previous
#include <cuda_runtime.h>
#include <cuda_fp16.h>
#include <cstdint>
#include <math.h>

// Problem constants
#define N_IMG 4
#define C_IN  256
#define HW    16384        // 128*128
#define MLP   128
#define NA    16
#define NB    64
#define ALPHA 300.0f

// ---------------------------------------------------------------------------
// SMEM layout (bytes). h aliases w1 (w1 dead after GEMM1); z aliases x bufs.
//   w1 tile [o=128][k=256] fp16, row pitch 528B (264 halves)   -> 67584
//   h  tile [o=128][p=128] fp16, row pitch 272B (136 halves)   -> 34816 (alias w1)
//   w2 tile [a=16][o=128]  fp16, row pitch 272B                -> 4352
//   x  bufs 2 x [k=16][p=128] fp16, row pitch 272B             -> 8704
//   z       [p=128][a=16+1] f32  (pitch 68B)                   -> 8704 (alias x)
//   b1 512B, b2 64B
// ---------------------------------------------------------------------------
#define W1_OFF 0
#define H_OFF  0
#define W2_OFF 67584
#define X_OFF  71936
#define XBUF_SZ 4352
#define Z_OFF  71936
#define B1_OFF 80640
#define B2_OFF 81152
#define SMEM_TOTAL 81216

#define W1_PITCH 528
#define X_PITCH  272
#define H_PITCH  272
#define W2_PITCH 272
#define Z_PITCH  68

__device__ __forceinline__ uint32_t smem_u32(const void* p) {
    uint32_t a;
    asm("{ .reg .u64 t; cvta.to.shared.u64 t, %1; cvt.u32.u64 %0, t; }" : "=r"(a) : "l"(p));
    return a;
}

__device__ __forceinline__ void ldsm_x4(uint32_t& r0, uint32_t& r1, uint32_t& r2, uint32_t& r3,
                                        uint32_t addr) {
    asm volatile("ldmatrix.sync.aligned.m8n8.x4.shared.b16 {%0,%1,%2,%3}, [%4];"
                 : "=r"(r0), "=r"(r1), "=r"(r2), "=r"(r3) : "r"(addr));
}
__device__ __forceinline__ void ldsm_x4_t(uint32_t& r0, uint32_t& r1, uint32_t& r2, uint32_t& r3,
                                          uint32_t addr) {
    asm volatile("ldmatrix.sync.aligned.m8n8.x4.trans.shared.b16 {%0,%1,%2,%3}, [%4];"
                 : "=r"(r0), "=r"(r1), "=r"(r2), "=r"(r3) : "r"(addr));
}
__device__ __forceinline__ void mma16816(float* c, const uint32_t* a, const uint32_t* b) {
    asm volatile(
        "mma.sync.aligned.m16n8k16.row.col.f32.f16.f16.f32 "
        "{%0,%1,%2,%3}, {%4,%5,%6,%7}, {%8,%9}, {%0,%1,%2,%3};"
        : "+f"(c[0]), "+f"(c[1]), "+f"(c[2]), "+f"(c[3])
        : "r"(a[0]), "r"(a[1]), "r"(a[2]), "r"(a[3]), "r"(b[0]), "r"(b[1]));
}

extern __shared__ char smem[];

// ---------------------------------------------------------------------------
// Fused kernel: 128 pixels per block, 256 threads (8 warps).
// GEMM1 (HMMA):  h[o=128][p=128] = w1[o][k=256] @ x^T      (fp16 in, f32 acc)
// GEMM2 (HMMA):  z[a=16][p=128]  = w2[a][o=128] @ relu(h+b1)
// Epilogue: softplus -> attractor update (64 bins x 16 attractors) -> out.
// ---------------------------------------------------------------------------
__global__ __launch_bounds__(256, 2) void fused_kernel(
    const float* __restrict__ x,
    const float* __restrict__ w1,
    const float* __restrict__ b1,
    const float* __restrict__ w2,
    const float* __restrict__ b2,
    const float* __restrict__ b_prev,
    float* __restrict__ out,
    int copies)
{
    const int tid = threadIdx.x;
    const int L = tid & 31;          // lane
    const int wid = tid >> 5;        // warp 0..7
    const int pix_base = blockIdx.x * 128;
    const int img = pix_base >> 14;
    const int hw0 = pix_base & (HW - 1);
    const uint32_t sb = smem_u32(smem);

    const float* xg = x + (size_t)img * C_IN * HW + hw0;

    // ---- stage weights + biases into smem (fp16 convert inline) ----
    {
#pragma unroll
        for (int i = 0; i < 64; i++) {           // w1: 16384 pairs
            int idx = tid + i * 256;
            int o = idx >> 7, kp = idx & 127;
            float2 v = *(const float2*)(w1 + o * C_IN + 2 * kp);
            __half2 h = __floats2half2_rn(v.x, v.y);
            *(uint32_t*)(smem + W1_OFF + o * W1_PITCH + kp * 4) = *(uint32_t*)&h;
        }
#pragma unroll
        for (int i = 0; i < 4; i++) {            // w2: 1024 pairs
            int idx = tid + i * 256;
            int a = idx >> 6, op = idx & 63;
            float2 v = *(const float2*)(w2 + a * MLP + 2 * op);
            __half2 h = __floats2half2_rn(v.x, v.y);
            *(uint32_t*)(smem + W2_OFF + a * W2_PITCH + op * 4) = *(uint32_t*)&h;
        }
        if (tid < 128) ((float*)(smem + B1_OFF))[tid] = b1[tid];
        if (tid < 16)  ((float*)(smem + B2_OFF))[tid] = b2[tid];
    }

    // ---- x tile loader: kstep s (16 k-rows x 128 pixels) -> fp16 smem [k][p] ----
    auto load_x = [&](int s, int buf) {
        char* xb = smem + X_OFF + buf * XBUF_SZ;
#pragma unroll
        for (int i = 0; i < 4; i++) {
            int pidx = tid + i * 256;            // 0..1023 pairs
            int kr = pidx >> 6, pp = pidx & 63;
            float2 v = *(const float2*)(xg + (size_t)(s * 16 + kr) * HW + 2 * pp);
            __half2 h = __floats2half2_rn(v.x, v.y);
            *(uint32_t*)(xb + kr * X_PITCH + pp * 4) = *(uint32_t*)&h;
        }
    };

    load_x(0, 0);
    __syncthreads();

    // ---- GEMM1: warp wid owns pixels p0..p0+15 (2 n-tiles), all 128 o ----
    const int p0 = wid * 16;
    float acc[8][2][4];
#pragma unroll
    for (int mt = 0; mt < 8; mt++)
#pragma unroll
        for (int nt = 0; nt < 2; nt++)
#pragma unroll
            for (int j = 0; j < 4; j++) acc[mt][nt][j] = 0.0f;

    const int lrow = L & 15;          // ldmatrix row index within 16
    const int lcol8 = (L >> 4) * 8;   // ldmatrix col-half select

    for (int s = 0; s < 16; s++) {
        if (s + 1 < 16) load_x(s + 1, (s + 1) & 1);

        uint32_t b[4];
        uint32_t addrB = sb + X_OFF + (s & 1) * XBUF_SZ
                       + (uint32_t)lrow * X_PITCH + (uint32_t)(p0 + lcol8) * 2;
        ldsm_x4_t(b[0], b[1], b[2], b[3], addrB);
#pragma unroll
        for (int mt = 0; mt < 8; mt++) {
            uint32_t a[4];
            uint32_t addrA = sb + W1_OFF + (uint32_t)(mt * 16 + lrow) * W1_PITCH
                           + (uint32_t)(s * 16 + lcol8) * 2;
            ldsm_x4(a[0], a[1], a[2], a[3], addrA);
            mma16816(acc[mt][0], a, b + 0);
            mma16816(acc[mt][1], a, b + 2);
        }
        __syncthreads();
    }

    // ---- epilogue 1: +b1, relu, fp16-pack -> h smem [o][p] (aliases w1) ----
    {
        const float* b1s = (const float*)(smem + B1_OFF);
        const int q2 = 2 * (L & 3);              // col pair base within n8
#pragma unroll
        for (int mt = 0; mt < 8; mt++) {
            int o0 = mt * 16 + (L >> 2);
            int o1 = o0 + 8;
            float bo0 = b1s[o0], bo1 = b1s[o1];
#pragma unroll
            for (int nt = 0; nt < 2; nt++) {
                int pc = p0 + nt * 8 + q2;
                float v0 = fmaxf(acc[mt][nt][0] + bo0, 0.0f);
                float v1 = fmaxf(acc[mt][nt][1] + bo0, 0.0f);
                float v2 = fmaxf(acc[mt][nt][2] + bo1, 0.0f);
                float v3 = fmaxf(acc[mt][nt][3] + bo1, 0.0f);
                __half2 h01 = __floats2half2_rn(v0, v1);
                __half2 h23 = __floats2half2_rn(v2, v3);
                *(uint32_t*)(smem + H_OFF + o0 * H_PITCH + pc * 2) = *(uint32_t*)&h01;
                *(uint32_t*)(smem + H_OFF + o1 * H_PITCH + pc * 2) = *(uint32_t*)&h23;
            }
        }
    }
    __syncthreads();

    // ---- GEMM2: z[a=16][p], k = o = 128 (8 ksteps) ----
    float zacc[2][4];
#pragma unroll
    for (int nt = 0; nt < 2; nt++)
#pragma unroll
        for (int j = 0; j < 4; j++) zacc[nt][j] = 0.0f;

    for (int s2 = 0; s2 < 8; s2++) {
        uint32_t b[4], a[4];
        uint32_t addrB = sb + H_OFF + (uint32_t)(s2 * 16 + lrow) * H_PITCH
                       + (uint32_t)(p0 + lcol8) * 2;
        ldsm_x4_t(b[0], b[1], b[2], b[3], addrB);
        uint32_t addrA = sb + W2_OFF + (uint32_t)lrow * W2_PITCH
                       + (uint32_t)(s2 * 16 + lcol8) * 2;
        ldsm_x4(a[0], a[1], a[2], a[3], addrA);
        mma16816(zacc[0], a, b + 0);
        mma16816(zacc[1], a, b + 2);
    }

    // ---- +b2, softplus -> z smem [p][a] f32 (aliases x bufs; x is dead) ----
    __syncthreads();   // all ldsm reads of x/h done before aliasing writes
    {
        const float* b2s = (const float*)(smem + B2_OFF);
        int a0r = L >> 2, a1r = a0r + 8;
        float ba0 = b2s[a0r], ba1 = b2s[a1r];
        const int q2 = 2 * (L & 3);
#pragma unroll
        for (int nt = 0; nt < 2; nt++) {
            int pc = p0 + nt * 8 + q2;
            float z0 = zacc[nt][0] + ba0;
            float z1 = zacc[nt][1] + ba0;
            float z2 = zacc[nt][2] + ba1;
            float z3 = zacc[nt][3] + ba1;
            float s0 = fmaxf(z0, 0.0f) + log1pf(__expf(-fabsf(z0)));
            float s1 = fmaxf(z1, 0.0f) + log1pf(__expf(-fabsf(z1)));
            float s2 = fmaxf(z2, 0.0f) + log1pf(__expf(-fabsf(z2)));
            float s3 = fmaxf(z3, 0.0f) + log1pf(__expf(-fabsf(z3)));
            float* zr0 = (float*)(smem + Z_OFF + (size_t)pc * Z_PITCH);
            float* zr1 = (float*)(smem + Z_OFF + (size_t)(pc + 1) * Z_PITCH);
            zr0[a0r] = s0;  zr1[a0r] = s1;
            zr0[a1r] = s2;  zr1[a1r] = s3;
        }
    }
    __syncthreads();

    // ---- attractor: 2 threads per pixel, 32 bins each, 16 attractors ----
    {
        const int p = tid & 127;
        const int half = tid >> 7;
        float Av[NA];
        const float* zr = (const float*)(smem + Z_OFF + (size_t)p * Z_PITCH);
#pragma unroll
        for (int a = 0; a < NA; a++) Av[a] = zr[a];

        const int gpix = hw0 + p;
        const float* bp = b_prev + (size_t)img * NB * HW + gpix + (size_t)(half * 32) * HW;
        float* o0 = out + (size_t)img * NB * HW + gpix + (size_t)(half * 32) * HW;
        float* o1 = o0 + (size_t)N_IMG * NB * HW;
        const float C = -ALPHA;
#pragma unroll 4
        for (int b = 0; b < 32; b++) {
            float bc = bp[(size_t)b * HW];
            float delta = 0.0f;
#pragma unroll
            for (int a = 0; a < NA; a++) {
                float dx = Av[a] - bc;
                float e = __expf(C * dx * dx);
                delta = fmaf(e, dx, delta);
            }
            float r = bc + delta;
            o0[(size_t)b * HW] = r;
            if (copies >= 2) o1[(size_t)b * HW] = r;
        }
    }
}

// ---------------------------------------------------------------------------
// Launch. Inputs (metadata order): x, b_prev, w1, b1, w2, b2.
// ---------------------------------------------------------------------------
extern "C" void kernel_launch(void* const* d_in, const int* in_sizes, int n_in,
                              void* d_out, int out_size) {
    const float* x      = (const float*)d_in[0];
    const float* b_prev = (const float*)d_in[1];
    const float* w1     = (const float*)d_in[2];
    const float* b1     = (const float*)d_in[3];
    const float* w2     = (const float*)d_in[4];
    const float* b2     = (const float*)d_in[5];
    float* out = (float*)d_out;

    const int one_out = N_IMG * NB * HW;
    int copies = out_size / one_out;

    static bool attr_set = false;
    if (!attr_set) {
        cudaFuncSetAttribute(fused_kernel,
                             cudaFuncAttributeMaxDynamicSharedMemorySize, SMEM_TOTAL);
        attr_set = true;
    }

    fused_kernel<<<(N_IMG * HW) / 128, 256, SMEM_TOTAL>>>(
        x, w1, b1, w2, b2, b_prev, out, copies);
}

// round 4
// speedup vs baseline: 2.9973x; 1.0764x over previous
#include <cuda_runtime.h>
#include <cuda_fp16.h>
#include <cstdint>
#include <math.h>

// Problem constants
#define N_IMG 4
#define C_IN  256
#define HW    16384        // 128*128
#define MLP   128
#define NA    16
#define NB    64
#define ALPHA 300.0f

// ---------------------------------------------------------------------------
// SMEM layout (bytes)
//   w1 [o=128][k=256] fp16, pitch 528    -> 67584
//   w2 [a=16][o=128]  fp16, pitch 272    -> 4352
//   x  per-warp 2 bufs [k=16][p=16] fp16, pitch 48 -> 8*2*768 = 12288
//   z  [p=128][a=16]  f32, pitch 80      -> 10240
//   b1 512, b2 64
// ---------------------------------------------------------------------------
#define W1_OFF   0
#define W2_OFF   67584
#define XB_OFF   71936
#define Z_OFF    84224
#define B1S_OFF  94464
#define B2S_OFF  94976
#define SMEM_TOTAL 95040

#define W1_PITCH 528
#define W2_PITCH 272
#define XB_PITCH 48
#define Z_PITCH  80

__device__ __forceinline__ uint32_t smem_u32(const void* p) {
    uint32_t a;
    asm("{ .reg .u64 t; cvta.to.shared.u64 t, %1; cvt.u32.u64 %0, t; }" : "=r"(a) : "l"(p));
    return a;
}
__device__ __forceinline__ void ldsm_x4(uint32_t& r0, uint32_t& r1, uint32_t& r2, uint32_t& r3,
                                        uint32_t addr) {
    asm volatile("ldmatrix.sync.aligned.m8n8.x4.shared.b16 {%0,%1,%2,%3}, [%4];"
                 : "=r"(r0), "=r"(r1), "=r"(r2), "=r"(r3) : "r"(addr));
}
__device__ __forceinline__ void ldsm_x4_t(uint32_t& r0, uint32_t& r1, uint32_t& r2, uint32_t& r3,
                                          uint32_t addr) {
    asm volatile("ldmatrix.sync.aligned.m8n8.x4.trans.shared.b16 {%0,%1,%2,%3}, [%4];"
                 : "=r"(r0), "=r"(r1), "=r"(r2), "=r"(r3) : "r"(addr));
}
__device__ __forceinline__ void mma16816(float* c, const uint32_t* a, const uint32_t* b) {
    asm volatile(
        "mma.sync.aligned.m16n8k16.row.col.f32.f16.f16.f32 "
        "{%0,%1,%2,%3}, {%4,%5,%6,%7}, {%8,%9}, {%0,%1,%2,%3};"
        : "+f"(c[0]), "+f"(c[1]), "+f"(c[2]), "+f"(c[3])
        : "r"(a[0]), "r"(a[1]), "r"(a[2]), "r"(a[3]), "r"(b[0]), "r"(b[1]));
}
__device__ __forceinline__ uint32_t h2exp2_u(uint32_t arg) {
    uint32_t r;
    asm("ex2.approx.f16x2 %0, %1;" : "=r"(r) : "r"(arg));
    return r;
}

// fp16 weights prepacked once (allocation-free: __device__ globals)
__device__ uint4 g_w1v[4096];    // w1 [o=128][k=256] halves, 8 per uint4
__device__ uint4 g_w2v[256];     // w2 [a=16][o=128]

__global__ void prep_kernel(const float* __restrict__ w1, const float* __restrict__ w2) {
    int i = blockIdx.x * 256 + threadIdx.x;
    const float* src;
    uint4* dst;
    if (i < 4096)      { src = w1 + 8 * i;          dst = &g_w1v[i]; }
    else if (i < 4352) { src = w2 + 8 * (i - 4096); dst = &g_w2v[i - 4096]; }
    else return;
    __half2 h0 = __floats2half2_rn(src[0], src[1]);
    __half2 h1 = __floats2half2_rn(src[2], src[3]);
    __half2 h2 = __floats2half2_rn(src[4], src[5]);
    __half2 h3 = __floats2half2_rn(src[6], src[7]);
    uint4 v;
    v.x = *(uint32_t*)&h0; v.y = *(uint32_t*)&h1;
    v.z = *(uint32_t*)&h2; v.w = *(uint32_t*)&h3;
    *dst = v;
}

extern __shared__ char smem[];

// ---------------------------------------------------------------------------
// Fused: 128 pixels/block, 256 thr (8 warps, each owns 16 pixels end-to-end).
// GEMM1: h_t[p16][o128] = x[p][k256] @ w1^T  (warp-local, no block syncs)
// GEMM2: z[p16][a16]    = relu(h_t+b1) @ w2^T  (C->A register reuse)
// softplus -> z smem; one __syncthreads; block-wide attractor (fp16x2 exp).
// ---------------------------------------------------------------------------
__global__ __launch_bounds__(256, 2) void fused_kernel(
    const float* __restrict__ x,
    const float* __restrict__ b1,
    const float* __restrict__ b2,
    const float* __restrict__ b_prev,
    float* __restrict__ out,
    int copies)
{
    const int tid = threadIdx.x;
    const int L   = tid & 31;
    const int wid = tid >> 5;
    const int pix_base = blockIdx.x * 128;
    const int img = pix_base >> 14;
    const int hw0 = pix_base & (HW - 1);
    const uint32_t sb = smem_u32(smem);

    // ---- stage weights + biases (block-shared, one sync) ----
#pragma unroll
    for (int i = 0; i < 16; i++) {
        int idx = tid + i * 256;             // 0..4095
        int o = idx >> 5, kq = idx & 31;
        *(uint4*)(smem + W1_OFF + o * W1_PITCH + kq * 16) = g_w1v[idx];
    }
    {
        int a = tid >> 4, kq = tid & 15;
        *(uint4*)(smem + W2_OFF + a * W2_PITCH + kq * 16) = g_w2v[tid];
        if (tid < 128) ((float*)(smem + B1S_OFF))[tid] = b1[tid];
        if (tid < 16)  ((float*)(smem + B2S_OFF))[tid] = b2[tid];
    }

    // ---- per-warp x staging (16 pixels, double-buffered k-steps) ----
    const int p0 = wid * 16;
    const float* xg = x + (size_t)img * C_IN * HW + hw0 + p0;
    const int xc = L & 7;       // float2 column (pixel pair)
    const int xk = L >> 3;      // k sub-row 0..3
    char* xwarp = smem + XB_OFF + wid * (2 * 16 * XB_PITCH);

    auto ldg_x = [&](int s, float2* xt) {
#pragma unroll
        for (int j = 0; j < 4; j++)
            xt[j] = *(const float2*)(xg + (size_t)(s * 16 + xk + 4 * j) * HW + 2 * xc);
    };
    auto sts_x = [&](int s, const float2* xt) {
        char* xb = xwarp + (s & 1) * (16 * XB_PITCH);
#pragma unroll
        for (int j = 0; j < 4; j++) {
            __half2 h = __floats2half2_rn(xt[j].x, xt[j].y);
            *(uint32_t*)(xb + (xk + 4 * j) * XB_PITCH + xc * 4) = *(uint32_t*)&h;
        }
    };

    {
        float2 xt0[4];
        ldg_x(0, xt0);
        sts_x(0, xt0);
    }
    __syncthreads();   // weights visible to all; also orders warp's own x STS
    __syncwarp();

    // ---- GEMM1: C[p16][o128] in regs ----
    float acc[16][4];
#pragma unroll
    for (int nt = 0; nt < 16; nt++)
#pragma unroll
        for (int j = 0; j < 4; j++) acc[nt][j] = 0.0f;

    const uint32_t xls_base = sb + XB_OFF + wid * (2 * 16 * XB_PITCH)
                            + (uint32_t)(L & 15) * XB_PITCH + (uint32_t)(L >> 4) * 16;
    const uint32_t w_row  = (uint32_t)((L & 7) + ((L >> 4) << 3));
    const uint32_t w_colo = (uint32_t)(((L >> 3) & 1) << 3);
    const uint32_t w1ls_base = sb + W1_OFF + w_row * W1_PITCH + w_colo * 2;
    const uint32_t w2ls_base = sb + W2_OFF + w_row * W2_PITCH + w_colo * 2;

    for (int s = 0; s < 16; s++) {
        float2 xt[4];
        if (s < 15) ldg_x(s + 1, xt);

        uint32_t x0, x1, x2, x3;
        ldsm_x4_t(x0, x1, x2, x3, xls_base + (uint32_t)(s & 1) * (16 * XB_PITCH));
        uint32_t af[4] = {x0, x2, x1, x3};     // A frag (p-rows, k-cols)

#pragma unroll
        for (int nt2 = 0; nt2 < 8; nt2++) {
            uint32_t bw[4];
            ldsm_x4(bw[0], bw[1], bw[2], bw[3],
                    w1ls_base + (uint32_t)(nt2 * 16) * W1_PITCH + (uint32_t)(s * 16) * 2);
            mma16816(acc[2 * nt2],     af, bw);
            mma16816(acc[2 * nt2 + 1], af, bw + 2);
        }

        if (s < 15) {
            sts_x(s + 1, xt);
            __syncwarp();
        }
    }

    // ---- epilogue1: +b1, relu, pack fp16 -> A2 frags in regs ----
    uint32_t h2r[32];
    {
        const float2* b1f2 = (const float2*)(smem + B1S_OFF);
#pragma unroll
        for (int nt = 0; nt < 16; nt++) {
            float2 bb = b1f2[nt * 4 + (L & 3)];
            float v0 = fmaxf(acc[nt][0] + bb.x, 0.0f);
            float v1 = fmaxf(acc[nt][1] + bb.y, 0.0f);
            float v2 = fmaxf(acc[nt][2] + bb.x, 0.0f);
            float v3 = fmaxf(acc[nt][3] + bb.y, 0.0f);
            __half2 a01 = __floats2half2_rn(v0, v1);
            __half2 a23 = __floats2half2_rn(v2, v3);
            h2r[2 * nt]     = *(uint32_t*)&a01;
            h2r[2 * nt + 1] = *(uint32_t*)&a23;
        }
    }

    // ---- GEMM2: z[p16][a16], K = o = 128 (8 ksteps), A = h2r directly ----
    float zacc[2][4];
#pragma unroll
    for (int nt = 0; nt < 2; nt++)
#pragma unroll
        for (int j = 0; j < 4; j++) zacc[nt][j] = 0.0f;

#pragma unroll
    for (int s2 = 0; s2 < 8; s2++) {
        uint32_t bw[4];
        ldsm_x4(bw[0], bw[1], bw[2], bw[3], w2ls_base + (uint32_t)(s2 * 16) * 2);
        mma16816(zacc[0], &h2r[4 * s2], bw);
        mma16816(zacc[1], &h2r[4 * s2], bw + 2);
    }

    // ---- +b2, softplus -> z smem [px][a] ----
    {
        const float2* b2f2 = (const float2*)(smem + B2S_OFF);
        int prow = p0 + (L >> 2);
        int acol = 2 * (L & 3);
#pragma unroll
        for (int nt = 0; nt < 2; nt++) {
            float2 bb = b2f2[nt * 4 + (L & 3)];
            float z0 = zacc[nt][0] + bb.x;
            float z1 = zacc[nt][1] + bb.y;
            float z2 = zacc[nt][2] + bb.x;
            float z3 = zacc[nt][3] + bb.y;
            float s0 = fmaxf(z0, 0.0f) + log1pf(__expf(-fabsf(z0)));
            float s1 = fmaxf(z1, 0.0f) + log1pf(__expf(-fabsf(z1)));
            float s2v = fmaxf(z2, 0.0f) + log1pf(__expf(-fabsf(z2)));
            float s3 = fmaxf(z3, 0.0f) + log1pf(__expf(-fabsf(z3)));
            float2 lo = make_float2(s0, s1);
            float2 hi = make_float2(s2v, s3);
            *(float2*)(smem + Z_OFF + (size_t)prow * Z_PITCH + (nt * 8 + acol) * 4) = lo;
            *(float2*)(smem + Z_OFF + (size_t)(prow + 8) * Z_PITCH + (nt * 8 + acol) * 4) = hi;
        }
    }
    __syncthreads();

    // ---- attractor: thread t -> pixel t&127, half t>>7 owns 32 bins ----
    {
        const int px = tid & 127;
        const int half = tid >> 7;
        const float* zr = (const float*)(smem + Z_OFF + (size_t)px * Z_PITCH);
        float Av[NA];
#pragma unroll
        for (int q = 0; q < 4; q++) {
            float4 v = *(const float4*)(zr + 4 * q);
            Av[4 * q] = v.x; Av[4 * q + 1] = v.y; Av[4 * q + 2] = v.z; Av[4 * q + 3] = v.w;
        }

        const int gpix = hw0 + px;
        const float* bp = b_prev + (size_t)img * NB * HW + gpix + (size_t)(half * 32) * HW;
        float* o0 = out + (size_t)img * NB * HW + gpix + (size_t)(half * 32) * HW;
        float* o1 = o0 + (size_t)N_IMG * NB * HW;
        const __half2 KH2 = __float2half2_rn(-432.80852f);   // -ALPHA * log2(e)

#pragma unroll 4
        for (int b = 0; b < 32; b++) {
            float bc = bp[(size_t)b * HW];
            float d0 = 0.0f, d1 = 0.0f;
#pragma unroll
            for (int i = 0; i < 8; i++) {
                float dx0 = Av[2 * i]     - bc;
                float dx1 = Av[2 * i + 1] - bc;
                __half2 dh = __floats2half2_rn(dx0, dx1);
                __half2 t2 = __hmul2(dh, dh);
                __half2 ar = __hmul2(t2, KH2);
                uint32_t eu = h2exp2_u(*(uint32_t*)&ar);
                __half2 e2 = *(__half2*)&eu;
                d0 = fmaf(__low2float(e2),  dx0, d0);
                d1 = fmaf(__high2float(e2), dx1, d1);
            }
            float r = bc + d0 + d1;
            o0[(size_t)b * HW] = r;
            if (copies >= 2) o1[(size_t)b * HW] = r;
        }
    }
}

// ---------------------------------------------------------------------------
// Launch. Inputs (metadata order): x, b_prev, w1, b1, w2, b2.
// ---------------------------------------------------------------------------
extern "C" void kernel_launch(void* const* d_in, const int* in_sizes, int n_in,
                              void* d_out, int out_size) {
    const float* x      = (const float*)d_in[0];
    const float* b_prev = (const float*)d_in[1];
    const float* w1     = (const float*)d_in[2];
    const float* b1     = (const float*)d_in[3];
    const float* w2     = (const float*)d_in[4];
    const float* b2     = (const float*)d_in[5];
    float* out = (float*)d_out;

    const int one_out = N_IMG * NB * HW;
    int copies = out_size / one_out;

    static bool attr_set = false;
    if (!attr_set) {
        cudaFuncSetAttribute(fused_kernel,
                             cudaFuncAttributeMaxDynamicSharedMemorySize, SMEM_TOTAL);
        attr_set = true;
    }

    prep_kernel<<<17, 256>>>(w1, w2);
    fused_kernel<<<(N_IMG * HW) / 128, 256, SMEM_TOTAL>>>(
        x, b1, b2, b_prev, out, copies);
}

// round 6
// speedup vs baseline: 3.2990x; 1.1007x over previous
#include <cuda_runtime.h>
#include <cuda_fp16.h>
#include <cstdint>
#include <math.h>

// Problem constants
#define N_IMG 4
#define C_IN  256
#define HW    16384        // 128*128
#define MLP   128
#define NA    16
#define NB    64
#define ALPHA 300.0f

// ---------------------------------------------------------------------------
// SMEM layout (bytes)
//   w1 [o=128][k=256] fp16, pitch 528          -> 67584
//   w2 [a=16][o=128]  fp16, pitch 272          -> 4352
//   x  per-warp 3 bufs [k=16][p=16] fp16, pitch 48 -> 8*3*768 = 18432
//   z  per-warp [p=16][a=16] f32, pitch 80     -> 8*1280 = 10240
//   b1 512, b2 64
// ---------------------------------------------------------------------------
#define W1_OFF   0
#define W2_OFF   67584
#define XB_OFF   71936
#define Z_OFF    90368
#define B1S_OFF  100608
#define B2S_OFF  101120
#define SMEM_TOTAL 101184

#define W1_PITCH 528
#define W2_PITCH 272
#define XB_PITCH 48
#define XBUF_SZ  (16 * XB_PITCH)      // 768 per stage
#define Z_PITCH  80

__device__ __forceinline__ uint32_t smem_u32(const void* p) {
    uint32_t a;
    asm("{ .reg .u64 t; cvta.to.shared.u64 t, %1; cvt.u32.u64 %0, t; }" : "=r"(a) : "l"(p));
    return a;
}
__device__ __forceinline__ void ldsm_x4(uint32_t& r0, uint32_t& r1, uint32_t& r2, uint32_t& r3,
                                        uint32_t addr) {
    asm volatile("ldmatrix.sync.aligned.m8n8.x4.shared.b16 {%0,%1,%2,%3}, [%4];"
                 : "=r"(r0), "=r"(r1), "=r"(r2), "=r"(r3) : "r"(addr));
}
__device__ __forceinline__ void ldsm_x4_t(uint32_t& r0, uint32_t& r1, uint32_t& r2, uint32_t& r3,
                                          uint32_t addr) {
    asm volatile("ldmatrix.sync.aligned.m8n8.x4.trans.shared.b16 {%0,%1,%2,%3}, [%4];"
                 : "=r"(r0), "=r"(r1), "=r"(r2), "=r"(r3) : "r"(addr));
}
__device__ __forceinline__ void mma16816(float* c, const uint32_t* a, const uint32_t* b) {
    asm volatile(
        "mma.sync.aligned.m16n8k16.row.col.f32.f16.f16.f32 "
        "{%0,%1,%2,%3}, {%4,%5,%6,%7}, {%8,%9}, {%0,%1,%2,%3};"
        : "+f"(c[0]), "+f"(c[1]), "+f"(c[2]), "+f"(c[3])
        : "r"(a[0]), "r"(a[1]), "r"(a[2]), "r"(a[3]), "r"(b[0]), "r"(b[1]));
}
__device__ __forceinline__ uint32_t h2exp2_u(uint32_t arg) {
    uint32_t r;
    asm("ex2.approx.f16x2 %0, %1;" : "=r"(r) : "r"(arg));
    return r;
}

// fp16 weights prepacked once (allocation-free: __device__ globals)
__device__ uint4 g_w1v[4096];    // w1 [o=128][k=256] halves, 8 per uint4
__device__ uint4 g_w2v[256];     // w2 [a=16][o=128]

__global__ void prep_kernel(const float* __restrict__ w1, const float* __restrict__ w2) {
    int i = blockIdx.x * 256 + threadIdx.x;
    const float* src;
    uint4* dst;
    if (i < 4096)      { src = w1 + 8 * i;          dst = &g_w1v[i]; }
    else if (i < 4352) { src = w2 + 8 * (i - 4096); dst = &g_w2v[i - 4096]; }
    else return;
    __half2 h0 = __floats2half2_rn(src[0], src[1]);
    __half2 h1 = __floats2half2_rn(src[2], src[3]);
    __half2 h2 = __floats2half2_rn(src[4], src[5]);
    __half2 h3 = __floats2half2_rn(src[6], src[7]);
    uint4 v;
    v.x = *(uint32_t*)&h0; v.y = *(uint32_t*)&h1;
    v.z = *(uint32_t*)&h2; v.w = *(uint32_t*)&h3;
    *dst = v;
}

extern __shared__ char smem[];

// ---------------------------------------------------------------------------
// Fused: 128 pixels/block, 256 thr. Each warp owns 16 pixels END TO END with
// NO block-wide sync after weight staging:
//   x stage (3-deep smem pipeline) -> GEMM1 -> relu/pack -> GEMM2 ->
//   softplus -> warp-local z -> attractor -> out.
// ---------------------------------------------------------------------------
__global__ __launch_bounds__(256, 2) void fused_kernel(
    const float* __restrict__ x,
    const float* __restrict__ b1,
    const float* __restrict__ b2,
    const float* __restrict__ b_prev,
    float* __restrict__ out,
    int copies)
{
    const int tid = threadIdx.x;
    const int L   = tid & 31;
    const int wid = tid >> 5;
    const int pix_base = blockIdx.x * 128;
    const int img = pix_base >> 14;
    const int hw0 = pix_base & (HW - 1);
    const uint32_t sb = smem_u32(smem);

    // ---- stage weights + biases (block-shared; the only block barrier) ----
#pragma unroll
    for (int i = 0; i < 16; i++) {
        int idx = tid + i * 256;             // 0..4095
        int o = idx >> 5, kq = idx & 31;
        *(uint4*)(smem + W1_OFF + o * W1_PITCH + kq * 16) = g_w1v[idx];
    }
    {
        int a = tid >> 4, kq = tid & 15;
        *(uint4*)(smem + W2_OFF + a * W2_PITCH + kq * 16) = g_w2v[tid];
        if (tid < 128) ((float*)(smem + B1S_OFF))[tid] = b1[tid];
        if (tid < 16)  ((float*)(smem + B2S_OFF))[tid] = b2[tid];
    }

    // ---- per-warp x staging: LDG.128 x2/thread/step, 3-stage smem pipe ----
    const int p0 = wid * 16;
    const float* xg = x + (size_t)img * C_IN * HW + hw0 + p0;
    const int xr = L >> 1;          // k sub-row 0..15
    const int xq = L & 1;           // float4 column selector
    char* xwarp = smem + XB_OFF + wid * (3 * XBUF_SZ);

    auto ldg2 = [&](int s, float4* xt) {
        const float* row = xg + (size_t)(s * 16 + xr) * HW;
        xt[0] = *(const float4*)(row + 4 * xq);
        xt[1] = *(const float4*)(row + 4 * (xq + 2));
    };
    auto sts2 = [&](int buf, const float4* xt) {
        char* xb = xwarp + buf * XBUF_SZ;
        __half2 a0 = __floats2half2_rn(xt[0].x, xt[0].y);
        __half2 a1 = __floats2half2_rn(xt[0].z, xt[0].w);
        __half2 c0 = __floats2half2_rn(xt[1].x, xt[1].y);
        __half2 c1 = __floats2half2_rn(xt[1].z, xt[1].w);
        uint2 u0 = make_uint2(*(uint32_t*)&a0, *(uint32_t*)&a1);
        uint2 u1 = make_uint2(*(uint32_t*)&c0, *(uint32_t*)&c1);
        *(uint2*)(xb + xr * XB_PITCH + xq * 8)       = u0;
        *(uint2*)(xb + xr * XB_PITCH + (xq + 2) * 8) = u1;
    };

    float4 xt0[2], xt1[2];
    ldg2(0, xt0);
    ldg2(1, xt1);
    sts2(0, xt0);                    // buf0 <- s0
    __syncthreads();                 // weights visible; own buf0 ordered
    __syncwarp();

    // ---- GEMM1: C[p16][o128] in regs, 16 k-steps, prefetch depth 2 ----
    float acc[16][4];
#pragma unroll
    for (int nt = 0; nt < 16; nt++)
#pragma unroll
        for (int j = 0; j < 4; j++) acc[nt][j] = 0.0f;

    const uint32_t xls_base = sb + XB_OFF + wid * (3 * XBUF_SZ)
                            + (uint32_t)(L & 15) * XB_PITCH + (uint32_t)(L >> 4) * 16;
    const uint32_t w_row  = (uint32_t)((L & 7) + ((L >> 4) << 3));
    const uint32_t w_colo = (uint32_t)(((L >> 3) & 1) << 3);
    const uint32_t w1ls_base = sb + W1_OFF + w_row * W1_PITCH + w_colo * 2;
    const uint32_t w2ls_base = sb + W2_OFF + w_row * W2_PITCH + w_colo * 2;

#pragma unroll
    for (int s = 0; s < 16; s++) {
        // prefetch s+2 into the register set freed last iteration
        float4* xfree = (s & 1) ? xt1 : xt0;      // holds s's data: dead after sts(s) done
        float4* xhold = (s & 1) ? xt0 : xt1;      // holds s+1's data
        if (s + 2 < 16) ldg2(s + 2, xfree);

        uint32_t x0, x1, x2, x3;
        ldsm_x4_t(x0, x1, x2, x3, xls_base + (uint32_t)((s % 3) * XBUF_SZ));
        uint32_t af[4] = {x0, x2, x1, x3};

#pragma unroll
        for (int nt2 = 0; nt2 < 8; nt2++) {
            uint32_t bw[4];
            ldsm_x4(bw[0], bw[1], bw[2], bw[3],
                    w1ls_base + (uint32_t)(nt2 * 16) * W1_PITCH + (uint32_t)(s * 16) * 2);
            mma16816(acc[2 * nt2],     af, bw);
            mma16816(acc[2 * nt2 + 1], af, bw + 2);
        }

        if (s + 1 < 16) {
            sts2((s + 1) % 3, xhold);             // data loaded one full iter ago
            __syncwarp();
        }
    }

    // ---- epilogue1: +b1, relu, pack fp16 -> A2 frags in regs ----
    uint32_t h2r[32];
    {
        const float2* b1f2 = (const float2*)(smem + B1S_OFF);
#pragma unroll
        for (int nt = 0; nt < 16; nt++) {
            float2 bb = b1f2[nt * 4 + (L & 3)];
            float v0 = fmaxf(acc[nt][0] + bb.x, 0.0f);
            float v1 = fmaxf(acc[nt][1] + bb.y, 0.0f);
            float v2 = fmaxf(acc[nt][2] + bb.x, 0.0f);
            float v3 = fmaxf(acc[nt][3] + bb.y, 0.0f);
            __half2 a01 = __floats2half2_rn(v0, v1);
            __half2 a23 = __floats2half2_rn(v2, v3);
            h2r[2 * nt]     = *(uint32_t*)&a01;
            h2r[2 * nt + 1] = *(uint32_t*)&a23;
        }
    }

    // ---- GEMM2: z[p16][a16], K = 128 (8 ksteps), A = h2r in regs ----
    float zacc[2][4];
#pragma unroll
    for (int nt = 0; nt < 2; nt++)
#pragma unroll
        for (int j = 0; j < 4; j++) zacc[nt][j] = 0.0f;

#pragma unroll
    for (int s2 = 0; s2 < 8; s2++) {
        uint32_t bw[4];
        ldsm_x4(bw[0], bw[1], bw[2], bw[3], w2ls_base + (uint32_t)(s2 * 16) * 2);
        mma16816(zacc[0], &h2r[4 * s2], bw);
        mma16816(zacc[1], &h2r[4 * s2], bw + 2);
    }

    // ---- +b2, softplus -> warp-local z smem [p16][a16] ----
    char* warpz = smem + Z_OFF + wid * (16 * Z_PITCH);
    {
        const float2* b2f2 = (const float2*)(smem + B2S_OFF);
        int lrow = L >> 2;
        int acol = 2 * (L & 3);
#pragma unroll
        for (int nt = 0; nt < 2; nt++) {
            float2 bb = b2f2[nt * 4 + (L & 3)];
            float z0 = zacc[nt][0] + bb.x;
            float z1 = zacc[nt][1] + bb.y;
            float z2 = zacc[nt][2] + bb.x;
            float z3 = zacc[nt][3] + bb.y;
            float s0 = fmaxf(z0, 0.0f) + log1pf(__expf(-fabsf(z0)));
            float s1 = fmaxf(z1, 0.0f) + log1pf(__expf(-fabsf(z1)));
            float s2v = fmaxf(z2, 0.0f) + log1pf(__expf(-fabsf(z2)));
            float s3 = fmaxf(z3, 0.0f) + log1pf(__expf(-fabsf(z3)));
            *(float2*)(warpz + (size_t)lrow * Z_PITCH + (nt * 8 + acol) * 4)
                = make_float2(s0, s1);
            *(float2*)(warpz + (size_t)(lrow + 8) * Z_PITCH + (nt * 8 + acol) * 4)
                = make_float2(s2v, s3);
        }
    }
    __syncwarp();

    // ---- attractor: 2 lanes per pixel (16 px), 32 bins each ----
    {
        const int px_l = L & 15;
        const int half = L >> 4;
        const float* zr = (const float*)(warpz + (size_t)px_l * Z_PITCH);
        float Av[NA];
#pragma unroll
        for (int q = 0; q < 4; q++) {
            float4 v = *(const float4*)(zr + 4 * q);
            Av[4 * q] = v.x; Av[4 * q + 1] = v.y; Av[4 * q + 2] = v.z; Av[4 * q + 3] = v.w;
        }

        const int gpix = hw0 + p0 + px_l;
        const float* bp = b_prev + (size_t)img * NB * HW + gpix + (size_t)(half * 32) * HW;
        float* o0 = out + (size_t)img * NB * HW + gpix + (size_t)(half * 32) * HW;
        float* o1 = o0 + (size_t)N_IMG * NB * HW;
        const __half2 KH2 = __float2half2_rn(-432.80852f);   // -ALPHA * log2(e)

#pragma unroll 4
        for (int b = 0; b < 32; b++) {
            float bc = bp[(size_t)b * HW];
            float d0 = 0.0f, d1 = 0.0f;
#pragma unroll
            for (int i = 0; i < 8; i++) {
                float dx0 = Av[2 * i]     - bc;
                float dx1 = Av[2 * i + 1] - bc;
                __half2 dh = __floats2half2_rn(dx0, dx1);
                __half2 t2 = __hmul2(dh, dh);
                __half2 ar = __hmul2(t2, KH2);
                uint32_t eu = h2exp2_u(*(uint32_t*)&ar);
                __half2 e2 = *(__half2*)&eu;
                d0 = fmaf(__low2float(e2),  dx0, d0);
                d1 = fmaf(__high2float(e2), dx1, d1);
            }
            float r = bc + d0 + d1;
            o0[(size_t)b * HW] = r;
            if (copies >= 2) o1[(size_t)b * HW] = r;
        }
    }
}

// ---------------------------------------------------------------------------
// Launch. Inputs (metadata order): x, b_prev, w1, b1, w2, b2.
// ---------------------------------------------------------------------------
extern "C" void kernel_launch(void* const* d_in, const int* in_sizes, int n_in,
                              void* d_out, int out_size) {
    const float* x      = (const float*)d_in[0];
    const float* b_prev = (const float*)d_in[1];
    const float* w1     = (const float*)d_in[2];
    const float* b1     = (const float*)d_in[3];
    const float* w2     = (const float*)d_in[4];
    const float* b2     = (const float*)d_in[5];
    float* out = (float*)d_out;

    const int one_out = N_IMG * NB * HW;
    int copies = out_size / one_out;

    static bool attr_set = false;
    if (!attr_set) {
        cudaFuncSetAttribute(fused_kernel,
                             cudaFuncAttributeMaxDynamicSharedMemorySize, SMEM_TOTAL);
        attr_set = true;
    }

    prep_kernel<<<17, 256>>>(w1, w2);
    fused_kernel<<<(N_IMG * HW) / 128, 256, SMEM_TOTAL>>>(
        x, b1, b2, b_prev, out, copies);
}

// round 9
// speedup vs baseline: 3.4310x; 1.0400x over previous
#include <cuda_runtime.h>
#include <cuda_fp16.h>
#include <cstdint>
#include <math.h>

// Problem constants
#define N_IMG 4
#define C_IN  256
#define HW    16384        // 128*128
#define MLP   128
#define NA    16
#define NB    64
#define ALPHA 300.0f

// ---------------------------------------------------------------------------
// SMEM layout (bytes)
//   w1 [o=128][k=256] fp16, pitch 528                 -> 67584
//   w2 [a=16][o=128]  fp16, pitch 272                 -> 4352
//   x  4-stage ring [k=16][p=128] fp32, pitch 528     -> 33792
//   z  per-warp [p=16][a=16] f32, pitch 72            -> 9216
//   b1 512, b2 64
// ---------------------------------------------------------------------------
#define W1_OFF   0
#define W2_OFF   67584
#define XS_OFF   71936
#define Z_OFF    105728
#define B1S_OFF  114944
#define B2S_OFF  115456
#define SMEM_TOTAL 115520

#define W1_PITCH 528
#define W2_PITCH 272
#define XS_PITCH 528                  // 132 floats per k-row
#define XSTAGE_SZ (16 * XS_PITCH)     // 8448 per stage
#define Z_PITCH  72

__device__ __forceinline__ uint32_t smem_u32(const void* p) {
    uint32_t a;
    asm("{ .reg .u64 t; cvta.to.shared.u64 t, %1; cvt.u32.u64 %0, t; }" : "=r"(a) : "l"(p));
    return a;
}
__device__ __forceinline__ void ldsm_x4(uint32_t& r0, uint32_t& r1, uint32_t& r2, uint32_t& r3,
                                        uint32_t addr) {
    asm volatile("ldmatrix.sync.aligned.m8n8.x4.shared.b16 {%0,%1,%2,%3}, [%4];"
                 : "=r"(r0), "=r"(r1), "=r"(r2), "=r"(r3) : "r"(addr));
}
__device__ __forceinline__ void mma16816(float* c, const uint32_t* a, const uint32_t* b) {
    asm volatile(
        "mma.sync.aligned.m16n8k16.row.col.f32.f16.f16.f32 "
        "{%0,%1,%2,%3}, {%4,%5,%6,%7}, {%8,%9}, {%0,%1,%2,%3};"
        : "+f"(c[0]), "+f"(c[1]), "+f"(c[2]), "+f"(c[3])
        : "r"(a[0]), "r"(a[1]), "r"(a[2]), "r"(a[3]), "r"(b[0]), "r"(b[1]));
}
__device__ __forceinline__ uint32_t h2exp2_u(uint32_t arg) {
    uint32_t r;
    asm("ex2.approx.f16x2 %0, %1;" : "=r"(r) : "r"(arg));
    return r;
}
__device__ __forceinline__ uint32_t packh2(float a, float b) {
    __half2 h = __floats2half2_rn(a, b);
    return *(uint32_t*)&h;
}

// fp16 weights prepacked once (allocation-free: __device__ globals)
__device__ uint4 g_w1v[4096];    // w1 [o=128][k=256] halves, 8 per uint4
__device__ uint4 g_w2v[256];     // w2 [a=16][o=128]

__global__ void prep_kernel(const float* __restrict__ w1, const float* __restrict__ w2) {
    int i = blockIdx.x * 256 + threadIdx.x;
    const float* src;
    uint4* dst;
    if (i < 4096)      { src = w1 + 8 * i;          dst = &g_w1v[i]; }
    else if (i < 4352) { src = w2 + 8 * (i - 4096); dst = &g_w2v[i - 4096]; }
    else return;
    uint4 v;
    v.x = packh2(src[0], src[1]);
    v.y = packh2(src[2], src[3]);
    v.z = packh2(src[4], src[5]);
    v.w = packh2(src[6], src[7]);
    *dst = v;
}

extern __shared__ char smem[];

// ---------------------------------------------------------------------------
// Fused: 128 pixels/block, 256 thr (8 warps; each warp owns 16 pixels).
// x: block-cooperative cp.async.cg 4-stage ring (coalesced 512B rows, L1
//    bypass). A fragments built from fp32 smem via 8 conflict-free LDS + cvt.
// GEMM1 -> relu/pack (regs) -> GEMM2 -> softplus -> warp-local z -> attract.
// ---------------------------------------------------------------------------
__global__ __launch_bounds__(256, 2) void fused_kernel(
    const float* __restrict__ x,
    const float* __restrict__ b1,
    const float* __restrict__ b2,
    const float* __restrict__ b_prev,
    float* __restrict__ out,
    int copies)
{
    const int tid = threadIdx.x;
    const int L   = tid & 31;
    const int wid = tid >> 5;
    const int pix_base = blockIdx.x * 128;
    const int img = pix_base >> 14;
    const int hw0 = pix_base & (HW - 1);
    const uint32_t sb = smem_u32(smem);

    const float* xgb = x + (size_t)img * C_IN * HW + hw0;   // block x slice

    // ---- cp.async stage issue: 16 k-rows x 128 px fp32, 2 x 16B per thread ----
    const int c0r = tid >> 5,          c0q = tid & 31;          // chunk tid
    const int c1r = (tid + 256) >> 5,  c1q = tid & 31;          // chunk tid+256
    auto issue_stage = [&](int s) {
        uint32_t dst = sb + XS_OFF + (uint32_t)((s & 3) * XSTAGE_SZ);
        const float* s0 = xgb + (size_t)(s * 16 + c0r) * HW + c0q * 4;
        const float* s1 = xgb + (size_t)(s * 16 + c1r) * HW + c1q * 4;
        asm volatile("cp.async.cg.shared.global [%0], [%1], 16;"
                     :: "r"(dst + (uint32_t)(c0r * XS_PITCH + c0q * 16)), "l"(s0) : "memory");
        asm volatile("cp.async.cg.shared.global [%0], [%1], 16;"
                     :: "r"(dst + (uint32_t)(c1r * XS_PITCH + c1q * 16)), "l"(s1) : "memory");
        asm volatile("cp.async.commit_group;" ::: "memory");
    };

    issue_stage(0);
    issue_stage(1);

    // ---- stage weights + biases (overlaps with cp.async stages 0/1) ----
#pragma unroll
    for (int i = 0; i < 16; i++) {
        int idx = tid + i * 256;             // 0..4095
        int o = idx >> 5, kq = idx & 31;
        *(uint4*)(smem + W1_OFF + o * W1_PITCH + kq * 16) = g_w1v[idx];
    }
    {
        int a = tid >> 4, kq = tid & 15;
        *(uint4*)(smem + W2_OFF + a * W2_PITCH + kq * 16) = g_w2v[tid];
        if (tid < 128) ((float*)(smem + B1S_OFF))[tid] = b1[tid];
        if (tid < 16)  ((float*)(smem + B2S_OFF))[tid] = b2[tid];
    }

    asm volatile("cp.async.wait_group 1;" ::: "memory");   // stage 0 done
    __syncthreads();                                        // weights + stage 0 visible

    // ---- GEMM1: C[p16][o128] in regs, 16 k-steps ----
    const int p0 = wid * 16;
    float acc[16][4];
#pragma unroll
    for (int nt = 0; nt < 16; nt++)
#pragma unroll
        for (int j = 0; j < 4; j++) acc[nt][j] = 0.0f;

    const int g  = L >> 2;
    const int t2 = (L & 3) * 2;
    const uint32_t w_row  = (uint32_t)((L & 7) + ((L >> 4) << 3));
    const uint32_t w_colo = (uint32_t)(((L >> 3) & 1) << 3);
    const uint32_t w1ls_base = sb + W1_OFF + w_row * W1_PITCH + w_colo * 2;
    const uint32_t w2ls_base = sb + W2_OFF + w_row * W2_PITCH + w_colo * 2;

#pragma unroll
    for (int s = 0; s < 16; s++) {
        if (s + 2 < 16) issue_stage(s + 2);

        // A fragment from fp32 stage [k][p] (pitch 132 floats): conflict-free
        const float* xb = (const float*)(smem + XS_OFF + (s & 3) * XSTAGE_SZ);
        const float* pc  = xb + p0 + g;        // pixel column g
        const float* pc8 = pc + 8;             // pixel column g+8
        uint32_t af[4];
        af[0] = packh2(pc [ t2      * 132], pc [(t2 + 1) * 132]);
        af[1] = packh2(pc8[ t2      * 132], pc8[(t2 + 1) * 132]);
        af[2] = packh2(pc [(t2 + 8) * 132], pc [(t2 + 9) * 132]);
        af[3] = packh2(pc8[(t2 + 8) * 132], pc8[(t2 + 9) * 132]);

#pragma unroll
        for (int nt2 = 0; nt2 < 8; nt2++) {
            uint32_t bw[4];
            ldsm_x4(bw[0], bw[1], bw[2], bw[3],
                    w1ls_base + (uint32_t)(nt2 * 16) * W1_PITCH + (uint32_t)(s * 16) * 2);
            mma16816(acc[2 * nt2],     af, bw);
            mma16816(acc[2 * nt2 + 1], af, bw + 2);
        }

        if (s < 15) {
            if (s + 2 < 16) { asm volatile("cp.async.wait_group 1;" ::: "memory"); }
            else            { asm volatile("cp.async.wait_group 0;" ::: "memory"); }
            __syncthreads();
        }
    }

    // ---- epilogue1: +b1, relu, pack fp16 -> A2 frags in regs ----
    uint32_t h2r[32];
    {
        const float2* b1f2 = (const float2*)(smem + B1S_OFF);
#pragma unroll
        for (int nt = 0; nt < 16; nt++) {
            float2 bb = b1f2[nt * 4 + (L & 3)];
            float v0 = fmaxf(acc[nt][0] + bb.x, 0.0f);
            float v1 = fmaxf(acc[nt][1] + bb.y, 0.0f);
            float v2 = fmaxf(acc[nt][2] + bb.x, 0.0f);
            float v3 = fmaxf(acc[nt][3] + bb.y, 0.0f);
            h2r[2 * nt]     = packh2(v0, v1);
            h2r[2 * nt + 1] = packh2(v2, v3);
        }
    }

    // ---- GEMM2: z[p16][a16], K = 128 (8 ksteps), A = h2r in regs ----
    float zacc[2][4];
#pragma unroll
    for (int nt = 0; nt < 2; nt++)
#pragma unroll
        for (int j = 0; j < 4; j++) zacc[nt][j] = 0.0f;

#pragma unroll
    for (int s2 = 0; s2 < 8; s2++) {
        uint32_t bw[4];
        ldsm_x4(bw[0], bw[1], bw[2], bw[3], w2ls_base + (uint32_t)(s2 * 16) * 2);
        mma16816(zacc[0], &h2r[4 * s2], bw);
        mma16816(zacc[1], &h2r[4 * s2], bw + 2);
    }

    // ---- +b2, softplus -> warp-local z smem [p16][a16] ----
    char* warpz = smem + Z_OFF + wid * (16 * Z_PITCH);
    {
        const float2* b2f2 = (const float2*)(smem + B2S_OFF);
        int lrow = L >> 2;
        int acol = 2 * (L & 3);
#pragma unroll
        for (int nt = 0; nt < 2; nt++) {
            float2 bb = b2f2[nt * 4 + (L & 3)];
            float z0 = zacc[nt][0] + bb.x;
            float z1 = zacc[nt][1] + bb.y;
            float z2 = zacc[nt][2] + bb.x;
            float z3 = zacc[nt][3] + bb.y;
            float s0  = fmaxf(z0, 0.0f) + log1pf(__expf(-fabsf(z0)));
            float s1  = fmaxf(z1, 0.0f) + log1pf(__expf(-fabsf(z1)));
            float s2v = fmaxf(z2, 0.0f) + log1pf(__expf(-fabsf(z2)));
            float s3  = fmaxf(z3, 0.0f) + log1pf(__expf(-fabsf(z3)));
            *(float2*)(warpz + (size_t)lrow * Z_PITCH + (nt * 8 + acol) * 4)
                = make_float2(s0, s1);
            *(float2*)(warpz + (size_t)(lrow + 8) * Z_PITCH + (nt * 8 + acol) * 4)
                = make_float2(s2v, s3);
        }
    }
    __syncwarp();

    // ---- attractor: 2 lanes per pixel (16 px), 32 bins each ----
    {
        const int px_l = L & 15;
        const int half = L >> 4;
        const float* zr = (const float*)(warpz + (size_t)px_l * Z_PITCH);
        float Av[NA];
#pragma unroll
        for (int q = 0; q < 8; q++) {
            float2 v = *(const float2*)(zr + 2 * q);
            Av[2 * q] = v.x; Av[2 * q + 1] = v.y;
        }

        const int gpix = hw0 + p0 + px_l;
        const float* bp = b_prev + (size_t)img * NB * HW + gpix + (size_t)(half * 32) * HW;
        float* o0 = out + (size_t)img * NB * HW + gpix + (size_t)(half * 32) * HW;
        float* o1 = o0 + (size_t)N_IMG * NB * HW;
        const __half2 KH2 = __float2half2_rn(-432.80852f);   // -ALPHA * log2(e)

#pragma unroll 4
        for (int b = 0; b < 32; b++) {
            float bc = bp[(size_t)b * HW];
            float d0 = 0.0f, d1 = 0.0f;
#pragma unroll
            for (int i = 0; i < 8; i++) {
                float dx0 = Av[2 * i]     - bc;
                float dx1 = Av[2 * i + 1] - bc;
                __half2 dh = __floats2half2_rn(dx0, dx1);
                __half2 t2v = __hmul2(dh, dh);
                __half2 ar = __hmul2(t2v, KH2);
                uint32_t eu = h2exp2_u(*(uint32_t*)&ar);
                __half2 e2 = *(__half2*)&eu;
                d0 = fmaf(__low2float(e2),  dx0, d0);
                d1 = fmaf(__high2float(e2), dx1, d1);
            }
            float r = bc + d0 + d1;
            o0[(size_t)b * HW] = r;
            if (copies >= 2) o1[(size_t)b * HW] = r;
        }
    }
}

// ---------------------------------------------------------------------------
// Launch. Inputs (metadata order): x, b_prev, w1, b1, w2, b2.
// ---------------------------------------------------------------------------
extern "C" void kernel_launch(void* const* d_in, const int* in_sizes, int n_in,
                              void* d_out, int out_size) {
    const float* x      = (const float*)d_in[0];
    const float* b_prev = (const float*)d_in[1];
    const float* w1     = (const float*)d_in[2];
    const float* b1     = (const float*)d_in[3];
    const float* w2     = (const float*)d_in[4];
    const float* b2     = (const float*)d_in[5];
    float* out = (float*)d_out;

    const int one_out = N_IMG * NB * HW;
    int copies = out_size / one_out;

    static bool attr_set = false;
    if (!attr_set) {
        cudaFuncSetAttribute(fused_kernel,
                             cudaFuncAttributeMaxDynamicSharedMemorySize, SMEM_TOTAL);
        attr_set = true;
    }

    prep_kernel<<<17, 256>>>(w1, w2);
    fused_kernel<<<(N_IMG * HW) / 128, 256, SMEM_TOTAL>>>(
        x, b1, b2, b_prev, out, copies);
}

// round 10
// speedup vs baseline: 4.0761x; 1.1880x over previous
#include <cuda_runtime.h>
#include <cuda_fp16.h>
#include <cstdint>
#include <math.h>

// Problem constants
#define N_IMG 4
#define C_IN  256
#define HW    16384        // 128*128
#define MLP   128
#define NA    16
#define NB    64
#define ALPHA 300.0f

// ---------------------------------------------------------------------------
// SMEM layout (bytes)
//   w1 [o=128][k=256] fp16, pitch 528                 -> 67584
//   w2 [a=16][o=128]  fp16, pitch 272                 -> 4352
//   x  4-stage ring [k=16][p=128] fp32, pitch 528     -> 33792
//   z  per-warp [p=16][a=16] f32, pitch 72            -> 9216
//   b1 512, b2 64
// ---------------------------------------------------------------------------
#define W1_OFF   0
#define W2_OFF   67584
#define XS_OFF   71936
#define Z_OFF    105728
#define B1S_OFF  114944
#define B2S_OFF  115456
#define SMEM_TOTAL 115520

#define W1_PITCH 528
#define W2_PITCH 272
#define XS_PITCH 528                  // 132 floats per k-row
#define XSTAGE_SZ (16 * XS_PITCH)     // 8448 per stage
#define Z_PITCH  72

__device__ __forceinline__ uint32_t smem_u32(const void* p) {
    uint32_t a;
    asm("{ .reg .u64 t; cvta.to.shared.u64 t, %1; cvt.u32.u64 %0, t; }" : "=r"(a) : "l"(p));
    return a;
}
__device__ __forceinline__ void ldsm_x4(uint32_t& r0, uint32_t& r1, uint32_t& r2, uint32_t& r3,
                                        uint32_t addr) {
    asm volatile("ldmatrix.sync.aligned.m8n8.x4.shared.b16 {%0,%1,%2,%3}, [%4];"
                 : "=r"(r0), "=r"(r1), "=r"(r2), "=r"(r3) : "r"(addr));
}
__device__ __forceinline__ void mma16816(float* c, const uint32_t* a, const uint32_t* b) {
    asm volatile(
        "mma.sync.aligned.m16n8k16.row.col.f32.f16.f16.f32 "
        "{%0,%1,%2,%3}, {%4,%5,%6,%7}, {%8,%9}, {%0,%1,%2,%3};"
        : "+f"(c[0]), "+f"(c[1]), "+f"(c[2]), "+f"(c[3])
        : "r"(a[0]), "r"(a[1]), "r"(a[2]), "r"(a[3]), "r"(b[0]), "r"(b[1]));
}
__device__ __forceinline__ uint32_t h2exp2_u(uint32_t arg) {
    uint32_t r;
    asm("ex2.approx.f16x2 %0, %1;" : "=r"(r) : "r"(arg));
    return r;
}
__device__ __forceinline__ uint32_t packh2(float a, float b) {
    __half2 h = __floats2half2_rn(a, b);
    return *(uint32_t*)&h;
}

// fp16 weights prepacked once (allocation-free: __device__ globals)
__device__ uint4 g_w1v[4096];    // w1 [o=128][k=256] halves, 8 per uint4
__device__ uint4 g_w2v[256];     // w2 [a=16][o=128]

__global__ void prep_kernel(const float* __restrict__ w1, const float* __restrict__ w2) {
    int i = blockIdx.x * 256 + threadIdx.x;
    const float* src;
    uint4* dst;
    if (i < 4096)      { src = w1 + 8 * i;          dst = &g_w1v[i]; }
    else if (i < 4352) { src = w2 + 8 * (i - 4096); dst = &g_w2v[i - 4096]; }
    else return;
    uint4 v;
    v.x = packh2(src[0], src[1]);
    v.y = packh2(src[2], src[3]);
    v.z = packh2(src[4], src[5]);
    v.w = packh2(src[6], src[7]);
    *dst = v;
}

extern __shared__ char smem[];

// ---------------------------------------------------------------------------
// Fused: 128 pixels/block, 256 thr (8 warps; each warp owns 16 pixels).
// x: cp.async.cg 4-stage ring, prefetch depth 3. GEMM1 -> relu/pack (regs)
// -> GEMM2 -> softplus -> warp-local z -> all-half2 attractor -> out.
// ---------------------------------------------------------------------------
__global__ __launch_bounds__(256, 2) void fused_kernel(
    const float* __restrict__ x,
    const float* __restrict__ b1,
    const float* __restrict__ b2,
    const float* __restrict__ b_prev,
    float* __restrict__ out,
    int copies)
{
    const int tid = threadIdx.x;
    const int L   = tid & 31;
    const int wid = tid >> 5;
    const int pix_base = blockIdx.x * 128;
    const int img = pix_base >> 14;
    const int hw0 = pix_base & (HW - 1);
    const uint32_t sb = smem_u32(smem);

    const float* xgb = x + (size_t)img * C_IN * HW + hw0;   // block x slice

    // ---- cp.async stage issue: 16 k-rows x 128 px fp32, 2 x 16B per thread ----
    const int c0r = tid >> 5,          c0q = tid & 31;          // chunk tid
    const int c1r = (tid + 256) >> 5,  c1q = tid & 31;          // chunk tid+256
    auto issue_stage = [&](int s) {
        uint32_t dst = sb + XS_OFF + (uint32_t)((s & 3) * XSTAGE_SZ);
        const float* s0 = xgb + (size_t)(s * 16 + c0r) * HW + c0q * 4;
        const float* s1 = xgb + (size_t)(s * 16 + c1r) * HW + c1q * 4;
        asm volatile("cp.async.cg.shared.global [%0], [%1], 16;"
                     :: "r"(dst + (uint32_t)(c0r * XS_PITCH + c0q * 16)), "l"(s0) : "memory");
        asm volatile("cp.async.cg.shared.global [%0], [%1], 16;"
                     :: "r"(dst + (uint32_t)(c1r * XS_PITCH + c1q * 16)), "l"(s1) : "memory");
        asm volatile("cp.async.commit_group;" ::: "memory");
    };

    issue_stage(0);
    issue_stage(1);
    issue_stage(2);

    // ---- stage weights + biases (overlaps with cp.async stages 0-2) ----
#pragma unroll
    for (int i = 0; i < 16; i++) {
        int idx = tid + i * 256;             // 0..4095
        int o = idx >> 5, kq = idx & 31;
        *(uint4*)(smem + W1_OFF + o * W1_PITCH + kq * 16) = g_w1v[idx];
    }
    {
        int a = tid >> 4, kq = tid & 15;
        *(uint4*)(smem + W2_OFF + a * W2_PITCH + kq * 16) = g_w2v[tid];
        if (tid < 128) ((float*)(smem + B1S_OFF))[tid] = b1[tid];
        if (tid < 16)  ((float*)(smem + B2S_OFF))[tid] = b2[tid];
    }

    asm volatile("cp.async.wait_group 2;" ::: "memory");   // stage 0 done
    __syncthreads();                                        // weights + stage 0 visible

    // ---- GEMM1: C[p16][o128] in regs, 16 k-steps, prefetch depth 3 ----
    const int p0 = wid * 16;
    float acc[16][4];
#pragma unroll
    for (int nt = 0; nt < 16; nt++)
#pragma unroll
        for (int j = 0; j < 4; j++) acc[nt][j] = 0.0f;

    const int g  = L >> 2;
    const int t2 = (L & 3) * 2;
    const uint32_t w_row  = (uint32_t)((L & 7) + ((L >> 4) << 3));
    const uint32_t w_colo = (uint32_t)(((L >> 3) & 1) << 3);
    const uint32_t w1ls_base = sb + W1_OFF + w_row * W1_PITCH + w_colo * 2;
    const uint32_t w2ls_base = sb + W2_OFF + w_row * W2_PITCH + w_colo * 2;

#pragma unroll
    for (int s = 0; s < 16; s++) {
        if (s + 3 < 16) issue_stage(s + 3);   // slot (s-1)&3, freed by last sync

        // A fragment from fp32 stage [k][p] (pitch 132 floats): conflict-free
        const float* xb = (const float*)(smem + XS_OFF + (s & 3) * XSTAGE_SZ);
        const float* pc  = xb + p0 + g;        // pixel column g
        const float* pc8 = pc + 8;             // pixel column g+8
        uint32_t af[4];
        af[0] = packh2(pc [ t2      * 132], pc [(t2 + 1) * 132]);
        af[1] = packh2(pc8[ t2      * 132], pc8[(t2 + 1) * 132]);
        af[2] = packh2(pc [(t2 + 8) * 132], pc [(t2 + 9) * 132]);
        af[3] = packh2(pc8[(t2 + 8) * 132], pc8[(t2 + 9) * 132]);

#pragma unroll
        for (int nt2 = 0; nt2 < 8; nt2++) {
            uint32_t bw[4];
            ldsm_x4(bw[0], bw[1], bw[2], bw[3],
                    w1ls_base + (uint32_t)(nt2 * 16) * W1_PITCH + (uint32_t)(s * 16) * 2);
            mma16816(acc[2 * nt2],     af, bw);
            mma16816(acc[2 * nt2 + 1], af, bw + 2);
        }

        if (s < 15) {
            // need stage s+1 complete before next iteration's reads
            if (s <= 12)      { asm volatile("cp.async.wait_group 2;" ::: "memory"); }
            else if (s == 13) { asm volatile("cp.async.wait_group 1;" ::: "memory"); }
            else              { asm volatile("cp.async.wait_group 0;" ::: "memory"); }
            __syncthreads();
        }
    }

    // ---- epilogue1: +b1, relu, pack fp16 -> A2 frags in regs ----
    uint32_t h2r[32];
    {
        const float2* b1f2 = (const float2*)(smem + B1S_OFF);
#pragma unroll
        for (int nt = 0; nt < 16; nt++) {
            float2 bb = b1f2[nt * 4 + (L & 3)];
            float v0 = fmaxf(acc[nt][0] + bb.x, 0.0f);
            float v1 = fmaxf(acc[nt][1] + bb.y, 0.0f);
            float v2 = fmaxf(acc[nt][2] + bb.x, 0.0f);
            float v3 = fmaxf(acc[nt][3] + bb.y, 0.0f);
            h2r[2 * nt]     = packh2(v0, v1);
            h2r[2 * nt + 1] = packh2(v2, v3);
        }
    }

    // ---- GEMM2: z[p16][a16], K = 128 (8 ksteps), A = h2r in regs ----
    float zacc[2][4];
#pragma unroll
    for (int nt = 0; nt < 2; nt++)
#pragma unroll
        for (int j = 0; j < 4; j++) zacc[nt][j] = 0.0f;

#pragma unroll
    for (int s2 = 0; s2 < 8; s2++) {
        uint32_t bw[4];
        ldsm_x4(bw[0], bw[1], bw[2], bw[3], w2ls_base + (uint32_t)(s2 * 16) * 2);
        mma16816(zacc[0], &h2r[4 * s2], bw);
        mma16816(zacc[1], &h2r[4 * s2], bw + 2);
    }

    // ---- +b2, softplus -> warp-local z smem [p16][a16] ----
    char* warpz = smem + Z_OFF + wid * (16 * Z_PITCH);
    {
        const float2* b2f2 = (const float2*)(smem + B2S_OFF);
        int lrow = L >> 2;
        int acol = 2 * (L & 3);
#pragma unroll
        for (int nt = 0; nt < 2; nt++) {
            float2 bb = b2f2[nt * 4 + (L & 3)];
            float z0 = zacc[nt][0] + bb.x;
            float z1 = zacc[nt][1] + bb.y;
            float z2 = zacc[nt][2] + bb.x;
            float z3 = zacc[nt][3] + bb.y;
            float s0  = fmaxf(z0, 0.0f) + log1pf(__expf(-fabsf(z0)));
            float s1  = fmaxf(z1, 0.0f) + log1pf(__expf(-fabsf(z1)));
            float s2v = fmaxf(z2, 0.0f) + log1pf(__expf(-fabsf(z2)));
            float s3  = fmaxf(z3, 0.0f) + log1pf(__expf(-fabsf(z3)));
            *(float2*)(warpz + (size_t)lrow * Z_PITCH + (nt * 8 + acol) * 4)
                = make_float2(s0, s1);
            *(float2*)(warpz + (size_t)(lrow + 8) * Z_PITCH + (nt * 8 + acol) * 4)
                = make_float2(s2v, s3);
        }
    }
    __syncwarp();

    // ---- attractor: 2 lanes per pixel (16 px), 32 bins each, all-half2 ----
    {
        const int px_l = L & 15;
        const int half = L >> 4;
        const float* zr = (const float*)(warpz + (size_t)px_l * Z_PITCH);
        uint32_t AvH2[8];
#pragma unroll
        for (int q = 0; q < 8; q++) {
            float2 v = *(const float2*)(zr + 2 * q);
            AvH2[q] = packh2(v.x, v.y);
        }

        const int gpix = hw0 + p0 + px_l;
        const float* bp = b_prev + (size_t)img * NB * HW + gpix + (size_t)(half * 32) * HW;
        float* o0 = out + (size_t)img * NB * HW + gpix + (size_t)(half * 32) * HW;
        float* o1 = o0 + (size_t)N_IMG * NB * HW;
        const __half2 KH2 = __float2half2_rn(-432.80852f);   // -ALPHA * log2(e)

        for (int c = 0; c < 4; c++) {            // 4 chunks x 8 bins
            float bcv[8], rv[8];
#pragma unroll
            for (int j = 0; j < 8; j++)          // batch 8 LDGs (overlap latency)
                bcv[j] = bp[(size_t)(c * 8 + j) * HW];
#pragma unroll
            for (int j = 0; j < 8; j++) {
                float bc = bcv[j];
                __half2 bch = __float2half2_rn(bc);
                // i = 0 (mul form, no zero-init)
                __half2 dh0 = __hsub2(*(const __half2*)&AvH2[0], bch);
                __half2 t0  = __hmul2(dh0, dh0);
                __half2 ar0 = __hmul2(t0, KH2);
                uint32_t e0 = h2exp2_u(*(uint32_t*)&ar0);
                __half2 dacc = __hmul2(*(__half2*)&e0, dh0);
#pragma unroll
                for (int i = 1; i < 8; i++) {
                    __half2 dh = __hsub2(*(const __half2*)&AvH2[i], bch);
                    __half2 t  = __hmul2(dh, dh);
                    __half2 ar = __hmul2(t, KH2);
                    uint32_t eu = h2exp2_u(*(uint32_t*)&ar);
                    dacc = __hfma2(*(__half2*)&eu, dh, dacc);
                }
                rv[j] = bc + __low2float(dacc) + __high2float(dacc);
            }
#pragma unroll
            for (int j = 0; j < 8; j++) {
                o0[(size_t)(c * 8 + j) * HW] = rv[j];
                if (copies >= 2) o1[(size_t)(c * 8 + j) * HW] = rv[j];
            }
        }
    }
}

// ---------------------------------------------------------------------------
// Launch. Inputs (metadata order): x, b_prev, w1, b1, w2, b2.
// ---------------------------------------------------------------------------
extern "C" void kernel_launch(void* const* d_in, const int* in_sizes, int n_in,
                              void* d_out, int out_size) {
    const float* x      = (const float*)d_in[0];
    const float* b_prev = (const float*)d_in[1];
    const float* w1     = (const float*)d_in[2];
    const float* b1     = (const float*)d_in[3];
    const float* w2     = (const float*)d_in[4];
    const float* b2     = (const float*)d_in[5];
    float* out = (float*)d_out;

    const int one_out = N_IMG * NB * HW;
    int copies = out_size / one_out;

    static bool attr_set = false;
    if (!attr_set) {
        cudaFuncSetAttribute(fused_kernel,
                             cudaFuncAttributeMaxDynamicSharedMemorySize, SMEM_TOTAL);
        attr_set = true;
    }

    prep_kernel<<<17, 256>>>(w1, w2);
    fused_kernel<<<(N_IMG * HW) / 128, 256, SMEM_TOTAL>>>(
        x, b1, b2, b_prev, out, copies);
}